// round 16
// baseline (speedup 1.0000x reference)
#include <cuda_runtime.h>

typedef unsigned long long u64;

// ---------------- problem constants ----------------
#define B     4
#define A     256
#define KA    256                 // atom length
#define T     16384
#define PAD   128                 // KA/2
#define TOUT  16385               // conv output length
#define RES_N 16960               // resident residual length (zero tail for window reads)
#define FMS   16896               // fm row stride = 33 chunks * 512
#define NCH   33
#define NITER 16
#define NBLK  128                 // persistent grid
#define PBLK  32                  // blocks per batch

#define SWZF(j) ((j) + ((j) >> 5))            // float index swizzle
#define SMEM_DYN ((SWZF(RES_N - 1) + 1) * 4)  // persist dynamic smem (s_resf)
#define SMEM_DNF (256 * 66 * 4)               // conv_full dynamic smem (s_dnf)

// ---------------- device scratch ----------------
__device__ float    g_dn[A * KA];
__device__ float    g_fm[(size_t)B * A * FMS];
__device__ u64      g_cmax[B * A * NCH];
__device__ u64      g_hist[B * NITER];    // per-iteration winning keys
__device__ unsigned g_arrive4[B];

// ---------------- helpers ----------------
__device__ __forceinline__ u64 packkey(float v, unsigned flat) {
    unsigned u = __float_as_uint(v);
    u = (u & 0x80000000u) ? ~u : (u | 0x80000000u);
    return ((u64)u << 32) | (unsigned)(~flat);          // ties -> smallest flat
}
__device__ __forceinline__ u64 pack2(float lo, float hi) {
    u64 r;
    asm("mov.b64 %0, {%1, %2};" : "=l"(r) : "f"(lo), "f"(hi));
    return r;
}
__device__ __forceinline__ void unpack2(u64 v, float& lo, float& hi) {
    asm("mov.b64 {%0, %1}, %2;" : "=f"(lo), "=f"(hi) : "l"(v));
}
__device__ __forceinline__ void ffma2(u64& acc, u64 a, u64 b) {
    asm("fma.rn.f32x2 %0, %1, %2, %0;" : "+l"(acc) : "l"(a), "l"(b));
}
__device__ __forceinline__ u64 umax(u64 a, u64 b) { return a > b ? a : b; }

__device__ __forceinline__ void decode(u64 best, int& a, int& p, float& v) {
    const unsigned hiw = (unsigned)(best >> 32);
    const unsigned u = (hiw & 0x80000000u) ? (hiw & 0x7fffffffu) : ~hiw;
    const unsigned flat = ~(unsigned)(best & 0xffffffffu);
    a = flat / TOUT;
    p = flat % TOUT;
    v = __uint_as_float(u);
}

__device__ __forceinline__ float xpad(const float* __restrict__ x, int b, int t) {
    return (t >= PAD && t < PAD + T) ? x[b * T + (t - PAD)] : 0.f;
}

// per-batch grid barrier (PBLK blocks, all resident)
__device__ __forceinline__ void gridbar(int b, unsigned target) {
    __syncthreads();
    if (threadIdx.x == 0) {
        __threadfence();
        atomicAdd(&g_arrive4[b], 1u);
        while (*((volatile unsigned*)&g_arrive4[b]) < target) { }
        __threadfence();
    }
    __syncthreads();
}

// ---------------- setup: normalize atoms + zero scratch (fused) ----------------
__global__ void normd_kernel(const float* __restrict__ d) {
    const int a = blockIdx.x;
    const float v = d[a * KA + threadIdx.x];
    float ss = v * v;
    #pragma unroll
    for (int o = 16; o; o >>= 1) ss += __shfl_down_sync(0xffffffffu, ss, o);
    __shared__ float s[8];
    __shared__ float norm;
    if ((threadIdx.x & 31) == 0) s[threadIdx.x >> 5] = ss;
    __syncthreads();
    if (threadIdx.x == 0) {
        float tot = 0.f;
        #pragma unroll
        for (int i = 0; i < 8; i++) tot += s[i];
        norm = sqrtf(tot) + 1e-12f;
    }
    __syncthreads();
    g_dn[a * KA + threadIdx.x] = v / norm;

    if (threadIdx.x < 132) {
        const int bb = threadIdx.x / 33, cc = threadIdx.x % 33;
        g_cmax[(bb * A + a) * NCH + cc] = 0ull;
    }
    if (a == 0) {
        if (threadIdx.x < B) g_arrive4[threadIdx.x] = 0u;
        if (threadIdx.x < B * NITER) g_hist[threadIdx.x] = 0ull;
    }
}

// ---------------- full correlation: 512t x 64a blocks, dictionary staged once ----------------
// grid (33, 4, B), 256 thr. s_dnf[256][66] holds all 256 k for 64 atoms (dynamic).
// 4 t-subtiles of 128; each block's t-range = exactly one 512-chunk, so chunk
// keys accumulate in registers across subtiles -> one s_red pass per block.
__global__ void __launch_bounds__(256) conv_full_kernel(const float* __restrict__ x) {
    extern __shared__ float s_dnf[];       // [256][66]
    #define DNF(k, aa) s_dnf[(k) * 66 + (aa)]

    const int b = blockIdx.z;
    const int tblk = blockIdx.x * 512;
    const int a0 = blockIdx.y * 64;
    const int tid = threadIdx.x;
    const int w = tid >> 5, l = tid & 31;

    __shared__ u64 s_rp2[384];
    __shared__ u64 s_red[64];

    if (tid < 64) s_red[tid] = 0ull;
    // stage full dictionary chunk once: 64 atoms x 256 k
    for (int i = tid; i < 64 * 256; i += 256) {
        const int k = i & 255, aa = i >> 8;
        DNF(k, aa) = g_dn[(a0 + aa) * KA + k];
    }
    // zero pad row k=... none needed: dp prefetch reads k+1 <= 256? inner loop
    // reads DNF(k8+kk+1, .) with k8+kk max 255 -> index 256 would overflow.
    // Use prefetch guard: stage a zero row at k=256? s_dnf is 256 rows only.
    // Instead clamp: prefetch from row min(k+1, 255) (value unused on last k).

    const int tw = w * 16;
    u64 klo_acc = 0ull, khi_acc = 0ull;
    const int alo = a0 + 2 * l;
    float* __restrict__ rowlo = g_fm + (size_t)(b * A + alo) * FMS;
    float* __restrict__ rowhi = rowlo + FMS;

    #pragma unroll 1
    for (int sub = 0; sub < 4; ++sub) {
        const int tbase = tblk + sub * 128;

        __syncthreads();                   // protect s_rp2 readers (and staged dnf on sub 0)
        for (int j = tid; j < 384; j += 256) {
            const float r = xpad(x, b, tbase + j);
            s_rp2[j] = pack2(r, r);
        }
        __syncthreads();

        u64 acc2[16], rbuf[16];
        #pragma unroll
        for (int i = 0; i < 16; i++) acc2[i] = 0ull;
        #pragma unroll
        for (int j = 0; j < 16; j++) rbuf[j] = s_rp2[tw + j];

        u64 dp = *reinterpret_cast<const u64*>(&DNF(0, 2 * l));
        #pragma unroll 1
        for (int k16 = 0; k16 < 256; k16 += 16) {
            #pragma unroll
            for (int kk = 0; kk < 16; kk++) {
                const int kn = (k16 + kk + 1) & 255;     // clamp wrap (last value unused)
                const u64 dpn = *reinterpret_cast<const u64*>(&DNF(kn, 2 * l));
                #pragma unroll
                for (int i = 0; i < 16; i++)
                    ffma2(acc2[i], rbuf[(i + kk) & 15], dp);
                rbuf[kk] = s_rp2[tw + k16 + kk + 16];
                dp = dpn;
            }
        }

        float vlo[16], vhi[16];
        #pragma unroll
        for (int i = 0; i < 16; i++) unpack2(acc2[i], vlo[i], vhi[i]);

        const int t0 = tbase + tw;
        if (tbase + 128 <= TOUT) {
            #pragma unroll
            for (int q = 0; q < 4; q++) {
                float4 wl = make_float4(vlo[4*q], vlo[4*q+1], vlo[4*q+2], vlo[4*q+3]);
                float4 wh = make_float4(vhi[4*q], vhi[4*q+1], vhi[4*q+2], vhi[4*q+3]);
                *reinterpret_cast<float4*>(&rowlo[t0 + 4*q]) = wl;
                *reinterpret_cast<float4*>(&rowhi[t0 + 4*q]) = wh;
            }
            #pragma unroll
            for (int i = 0; i < 16; i++) {
                const int t = t0 + i;
                klo_acc = umax(klo_acc, packkey(vlo[i], (unsigned)(alo * TOUT + t)));
                khi_acc = umax(khi_acc, packkey(vhi[i], (unsigned)((alo + 1) * TOUT + t)));
            }
        } else {
            #pragma unroll
            for (int i = 0; i < 16; i++) {
                const int t = t0 + i;
                if (t < TOUT) {
                    rowlo[t] = vlo[i];
                    rowhi[t] = vhi[i];
                    klo_acc = umax(klo_acc, packkey(vlo[i], (unsigned)(alo * TOUT + t)));
                    khi_acc = umax(khi_acc, packkey(vhi[i], (unsigned)((alo + 1) * TOUT + t)));
                }
            }
        }
    }

    // one chunk-key reduction per block (whole 512-t range is one chunk)
    atomicMax(&s_red[2 * l],     klo_acc);
    atomicMax(&s_red[2 * l + 1], khi_acc);
    __syncthreads();
    if (tid < 64) {
        const int c = tblk >> 9;
        if (c < NCH)
            atomicMax(&g_cmax[(b * A + a0 + tid) * NCH + c], s_red[tid]);
    }
    #undef DNF
}

// ---------------- persistent iteration kernel (+ fused output epilogue) ----------------
__global__ void __launch_bounds__(512) persist_kernel(const float* __restrict__ x,
                                                      float* __restrict__ out) {
    extern __shared__ float s_resf[];      // SWZF-indexed private padded residual

    const int blk = blockIdx.x;
    const int b = blk >> 5;
    const int a0 = (blk & 31) * 8;
    const int tid = threadIdx.x;
    const int w = tid >> 5, l = tid & 31;

    __shared__ u64   s_dn2[258 * 4];       // [k][pair], +2 k rows for dp prefetch
    __shared__ u64   s_cm[8 * 33];         // chunk maxima for own 8 atoms
    __shared__ u64   s_red2[8];            // per-warp atom maxima (block reduce)
    __shared__ int   sh_a, sh_p;
    __shared__ float sh_v;

    for (int i = tid; i < 258 * 4; i += 512) {
        const int k = i >> 2, p = i & 3;
        s_dn2[i] = (k < 256) ? pack2(g_dn[(a0 + 2 * p) * KA + k],
                                     g_dn[(a0 + 2 * p + 1) * KA + k])
                             : 0ull;
    }
    for (int j = tid; j < RES_N; j += 512)
        s_resf[SWZF(j)] = xpad(x, b, j);

    // phase 0: initial chunk maxima -> smem, atom max -> s_red2, 1 ATOMG/block
    if (w < 8) {
        const u64* __restrict__ cm = g_cmax + (size_t)(b * A + a0 + w) * NCH;
        u64 v = cm[l];
        s_cm[w * 33 + l] = v;
        if (l == 0) {
            const u64 v32 = cm[32];
            s_cm[w * 33 + 32] = v32;
            v = umax(v, v32);
        }
        #pragma unroll
        for (int o = 16; o; o >>= 1) v = umax(v, __shfl_xor_sync(0xffffffffu, v, o));
        if (l == 0) s_red2[w] = v;
    }
    __syncthreads();
    if (tid == 0) {
        u64 v = s_red2[0];
        #pragma unroll
        for (int i = 1; i < 8; i++) v = umax(v, s_red2[i]);
        atomicMax(&g_hist[b * NITER + 0], v);
    }

    unsigned target = PBLK;
    gridbar(b, target);                    // hist[0] final

    for (int it = 1; it < NITER; ++it) {
        if (tid == 0) decode(g_hist[b * NITER + it - 1], sh_a, sh_p, sh_v);
        __syncthreads();

        const int pos = sh_p;
        const int sa  = sh_a;
        const float sv = sh_v;
        const int lo = max(0, pos - (KA - 1));
        const int hi = min(TOUT - 1, pos + (KA - 1));
        const int c0 = lo >> 9, c1 = hi >> 9;

        if (w >= 8) {
            const int k = (w - 8) * 32 + l;
            s_resf[SWZF(pos + k)] -= sv * g_dn[sa * KA + k];
        } else if (tid < 16) {
            const int at = tid >> 1;
            const int cc = (tid & 1) ? c1 : c0;
            s_cm[at * 33 + cc] = 0ull;
        }
        __syncthreads();

        if (w < 8) {
            const int p = w & 3, h = w >> 2;
            const int t0 = lo + h * 256 + l * 8;

            u64 acc2[8], rbuf[16];
            #pragma unroll
            for (int i = 0; i < 8; i++) acc2[i] = 0ull;
            #pragma unroll
            for (int j = 0; j < 16; j++) {
                const float r = s_resf[SWZF(t0 + j)];
                rbuf[j] = pack2(r, r);
            }

            u64 dp  = s_dn2[p];
            u64 dp1 = s_dn2[4 + p];
            #pragma unroll 1
            for (int k16 = 0; k16 < 256; k16 += 16) {
                #pragma unroll
                for (int kk = 0; kk < 16; kk++) {
                    const u64 dpn = s_dn2[(k16 + kk + 2) * 4 + p];
                    #pragma unroll
                    for (int i = 0; i < 8; i++)
                        ffma2(acc2[i], rbuf[(kk + i) & 15], dp);
                    const float r = s_resf[SWZF(t0 + k16 + kk + 16)];
                    rbuf[kk] = pack2(r, r);
                    dp = dp1; dp1 = dpn;
                }
            }

            float vlo[8], vhi[8];
            #pragma unroll
            for (int i = 0; i < 8; i++) unpack2(acc2[i], vlo[i], vhi[i]);

            const int alo = a0 + 2 * p;
            float* __restrict__ rowlo = g_fm + (size_t)(b * A + alo) * FMS;
            float* __restrict__ rowhi = rowlo + FMS;

            u64 blo0 = 0ull, blo1 = 0ull, bhi0 = 0ull, bhi1 = 0ull;
            #pragma unroll
            for (int i = 0; i < 8; i++) {
                const int t = t0 + i;
                if (t <= hi) {
                    rowlo[t] = vlo[i];
                    rowhi[t] = vhi[i];
                    const u64 klo = packkey(vlo[i], (unsigned)(alo * TOUT + t));
                    const u64 khi = packkey(vhi[i], (unsigned)((alo + 1) * TOUT + t));
                    if ((t >> 9) == c0) { blo0 = umax(blo0, klo); bhi0 = umax(bhi0, khi); }
                    else               { blo1 = umax(blo1, klo); bhi1 = umax(bhi1, khi); }
                }
            }
            #pragma unroll
            for (int o = 16; o; o >>= 1) {
                blo0 = umax(blo0, __shfl_xor_sync(0xffffffffu, blo0, o));
                blo1 = umax(blo1, __shfl_xor_sync(0xffffffffu, blo1, o));
                bhi0 = umax(bhi0, __shfl_xor_sync(0xffffffffu, bhi0, o));
                bhi1 = umax(bhi1, __shfl_xor_sync(0xffffffffu, bhi1, o));
            }
            if (l == 0) {
                atomicMax(&s_cm[(2 * p) * 33 + c0], blo0);
                atomicMax(&s_cm[(2 * p) * 33 + c1], blo1);
                atomicMax(&s_cm[(2 * p + 1) * 33 + c0], bhi0);
                atomicMax(&s_cm[(2 * p + 1) * 33 + c1], bhi1);
            }
        } else {
            const int aw = a0 + (w - 8);
            const int tstart = c0 << 9;
            const int tend = min((c1 + 1) << 9, TOUT);
            const float* __restrict__ rowa = g_fm + (size_t)(b * A + aw) * FMS;
            const unsigned fbase = (unsigned)(aw * TOUT);

            u64 b0 = 0ull, b1 = 0ull;
            #pragma unroll 4
            for (int t = tstart + l; t < tend; t += 32) {
                if (t < lo || t > hi) {
                    const u64 kq = packkey(rowa[t], fbase + t);
                    if ((t >> 9) == c0) b0 = umax(b0, kq); else b1 = umax(b1, kq);
                }
            }
            #pragma unroll
            for (int o = 16; o; o >>= 1) {
                b0 = umax(b0, __shfl_xor_sync(0xffffffffu, b0, o));
                b1 = umax(b1, __shfl_xor_sync(0xffffffffu, b1, o));
            }
            if (l == 0) {
                atomicMax(&s_cm[(w - 8) * 33 + c0], b0);
                atomicMax(&s_cm[(w - 8) * 33 + c1], b1);
            }
        }
        __syncthreads();

        if (w < 8) {
            u64 v = s_cm[w * 33 + l];
            if (l == 0) v = umax(v, s_cm[w * 33 + 32]);
            #pragma unroll
            for (int o = 16; o; o >>= 1)
                v = umax(v, __shfl_xor_sync(0xffffffffu, v, o));
            if (l == 0) s_red2[w] = v;
        }
        __syncthreads();
        if (tid == 0) {
            u64 v = s_red2[0];
            #pragma unroll
            for (int i = 1; i < 8; i++) v = umax(v, s_red2[i]);
            atomicMax(&g_hist[b * NITER + it], v);
        }

        target += PBLK;
        gridbar(b, target);                // hist[it] final
    }

    // ---- fused output epilogue: block writes its 512-output slice ----
    {
        __shared__ int   sa16[NITER], sp16[NITER];
        __shared__ float sv16[NITER];
        if (tid < NITER)
            decode(g_hist[b * NITER + tid], sa16[tid], sp16[tid], sv16[tid]);
        __syncthreads();

        const int t = (blk & 31) * 512 + tid;
        const int tp = t + PAD;
        float acc = 0.f;
        #pragma unroll 1
        for (int j = 0; j < NITER; ++j) {
            const int off = tp - sp16[j];
            if (off >= 0 && off < KA)
                acc += sv16[j] * g_dn[sa16[j] * KA + off];
        }
        out[b * T + t] = acc;
    }
}

// ---------------- launch ----------------
extern "C" void kernel_launch(void* const* d_in, const int* in_sizes, int n_in,
                              void* d_out, int out_size) {
    const float* x = (const float*)d_in[0];
    const float* d = (const float*)d_in[1];
    float* out = (float*)d_out;
    (void)in_sizes; (void)n_in; (void)out_size;

    static int configured = 0;
    if (!configured) {
        cudaFuncSetAttribute(persist_kernel,
                             cudaFuncAttributeMaxDynamicSharedMemorySize, SMEM_DYN);
        cudaFuncSetAttribute(conv_full_kernel,
                             cudaFuncAttributeMaxDynamicSharedMemorySize, SMEM_DNF);
        configured = 1;
    }

    normd_kernel<<<A, KA>>>(d);
    conv_full_kernel<<<dim3(33, 4, B), 256, SMEM_DNF>>>(x);
    persist_kernel<<<NBLK, 512, SMEM_DYN>>>(x, out);
}

// round 17
// speedup vs baseline: 1.0643x; 1.0643x over previous
#include <cuda_runtime.h>

typedef unsigned long long u64;

// ---------------- problem constants ----------------
#define B     4
#define A     256
#define KA    256                 // atom length
#define T     16384
#define PAD   128                 // KA/2
#define TOUT  16385               // conv output length
#define RES_N 16960               // resident residual length (zero tail for window reads)
#define FMS   16896               // fm row stride = 33 chunks * 512
#define NCH   33
#define NITER 16
#define NBLK  128                 // persistent grid
#define PBLK  32                  // blocks per batch

#define SWZF(j) ((j) + ((j) >> 5))            // float index swizzle
#define SMEM_DYN ((SWZF(RES_N - 1) + 1) * 4)  // persist dynamic smem (s_resf)

// ---------------- device scratch ----------------
__device__ float    g_dn[A * KA];
__device__ float    g_fm[(size_t)B * A * FMS];
__device__ u64      g_cmax[B * A * NCH];
__device__ u64      g_hist[B * NITER];    // per-iteration winning keys
__device__ unsigned g_arrive4[B];

// ---------------- helpers ----------------
__device__ __forceinline__ u64 packkey(float v, unsigned flat) {
    unsigned u = __float_as_uint(v);
    u = (u & 0x80000000u) ? ~u : (u | 0x80000000u);
    return ((u64)u << 32) | (unsigned)(~flat);          // ties -> smallest flat
}
__device__ __forceinline__ u64 pack2(float lo, float hi) {
    u64 r;
    asm("mov.b64 %0, {%1, %2};" : "=l"(r) : "f"(lo), "f"(hi));
    return r;
}
__device__ __forceinline__ void unpack2(u64 v, float& lo, float& hi) {
    asm("mov.b64 {%0, %1}, %2;" : "=f"(lo), "=f"(hi) : "l"(v));
}
__device__ __forceinline__ void ffma2(u64& acc, u64 a, u64 b) {
    asm("fma.rn.f32x2 %0, %1, %2, %0;" : "+l"(acc) : "l"(a), "l"(b));
}
__device__ __forceinline__ u64 umax(u64 a, u64 b) { return a > b ? a : b; }

__device__ __forceinline__ void decode(u64 best, int& a, int& p, float& v) {
    const unsigned hiw = (unsigned)(best >> 32);
    const unsigned u = (hiw & 0x80000000u) ? (hiw & 0x7fffffffu) : ~hiw;
    const unsigned flat = ~(unsigned)(best & 0xffffffffu);
    a = flat / TOUT;
    p = flat % TOUT;
    v = __uint_as_float(u);
}

__device__ __forceinline__ float xpad(const float* __restrict__ x, int b, int t) {
    return (t >= PAD && t < PAD + T) ? x[b * T + (t - PAD)] : 0.f;
}

// per-batch grid barrier (PBLK blocks, all resident)
__device__ __forceinline__ void gridbar(int b, unsigned target) {
    __syncthreads();
    if (threadIdx.x == 0) {
        __threadfence();
        atomicAdd(&g_arrive4[b], 1u);
        while (*((volatile unsigned*)&g_arrive4[b]) < target) { }
        __threadfence();
    }
    __syncthreads();
}

// ---------------- setup: normalize atoms + zero scratch (fused) ----------------
__global__ void normd_kernel(const float* __restrict__ d) {
    const int a = blockIdx.x;
    const float v = d[a * KA + threadIdx.x];
    float ss = v * v;
    #pragma unroll
    for (int o = 16; o; o >>= 1) ss += __shfl_down_sync(0xffffffffu, ss, o);
    __shared__ float s[8];
    __shared__ float norm;
    if ((threadIdx.x & 31) == 0) s[threadIdx.x >> 5] = ss;
    __syncthreads();
    if (threadIdx.x == 0) {
        float tot = 0.f;
        #pragma unroll
        for (int i = 0; i < 8; i++) tot += s[i];
        norm = sqrtf(tot) + 1e-12f;
    }
    __syncthreads();
    g_dn[a * KA + threadIdx.x] = v / norm;

    if (threadIdx.x < 132) {
        const int bb = threadIdx.x / 33, cc = threadIdx.x % 33;
        g_cmax[(bb * A + a) * NCH + cc] = 0ull;
    }
    if (a == 0) {
        if (threadIdx.x < B) g_arrive4[threadIdx.x] = 0u;
        if (threadIdx.x < B * NITER) g_hist[threadIdx.x] = 0ull;
    }
}

// ---------------- full correlation (128t x 64a, 256 thr; R10 shape) ----------------
__global__ void __launch_bounds__(256) conv_full_kernel(const float* __restrict__ x) {
    const int b = blockIdx.z;
    const int tbase = blockIdx.x * 128;
    const int a0 = blockIdx.y * 64;
    const int tid = threadIdx.x;
    const int w = tid >> 5, l = tid & 31;

    __shared__ float s_dnf[129][66];
    __shared__ u64   s_rp2[384];
    __shared__ u64   s_red[64];

    if (tid < 64) s_red[tid] = 0ull;
    if (tid < 66) s_dnf[128][tid] = 0.f;
    #pragma unroll 2
    for (int j = tid; j < 384; j += 256) {
        const float r = xpad(x, b, tbase + j);
        s_rp2[j] = pack2(r, r);
    }

    u64 acc2[16], rbuf[16];
    #pragma unroll
    for (int i = 0; i < 16; i++) acc2[i] = 0ull;

    const int tw = w * 16;

    #pragma unroll 1
    for (int kc = 0; kc < 256; kc += 128) {
        __syncthreads();
        #pragma unroll 8
        for (int i = tid; i < 64 * 128; i += 256) {
            const int k = i & 127, aa = i >> 7;
            s_dnf[k][aa] = g_dn[(a0 + aa) * KA + kc + k];
        }
        __syncthreads();
        if (kc == 0) {
            #pragma unroll
            for (int j = 0; j < 16; j++) rbuf[j] = s_rp2[tw + j];
        }
        u64 dp = *reinterpret_cast<const u64*>(&s_dnf[0][2 * l]);
        #pragma unroll 1
        for (int k8 = 0; k8 < 128; k8 += 16) {
            #pragma unroll
            for (int kk = 0; kk < 16; kk++) {
                const u64 dpn =
                    *reinterpret_cast<const u64*>(&s_dnf[k8 + kk + 1][2 * l]);
                #pragma unroll
                for (int i = 0; i < 16; i++)
                    ffma2(acc2[i], rbuf[(i + kk) & 15], dp);
                rbuf[kk] = s_rp2[tw + kc + k8 + kk + 16];
                dp = dpn;
            }
        }
    }

    float vlo[16], vhi[16];
    #pragma unroll
    for (int i = 0; i < 16; i++) unpack2(acc2[i], vlo[i], vhi[i]);

    const int alo = a0 + 2 * l;
    float* __restrict__ rowlo = g_fm + (size_t)(b * A + alo) * FMS;
    float* __restrict__ rowhi = rowlo + FMS;
    const int t0 = tbase + tw;

    if (tbase + 128 <= TOUT) {
        #pragma unroll
        for (int q = 0; q < 4; q++) {
            float4 wl = make_float4(vlo[4*q], vlo[4*q+1], vlo[4*q+2], vlo[4*q+3]);
            float4 wh = make_float4(vhi[4*q], vhi[4*q+1], vhi[4*q+2], vhi[4*q+3]);
            *reinterpret_cast<float4*>(&rowlo[t0 + 4*q]) = wl;
            *reinterpret_cast<float4*>(&rowhi[t0 + 4*q]) = wh;
        }
    } else {
        #pragma unroll
        for (int i = 0; i < 16; i++) {
            const int t = t0 + i;
            if (t < TOUT) { rowlo[t] = vlo[i]; rowhi[t] = vhi[i]; }
        }
    }

    u64 klo = 0ull, khi = 0ull;
    #pragma unroll
    for (int i = 0; i < 16; i++) {
        const int t = t0 + i;
        if (t < TOUT) {
            klo = umax(klo, packkey(vlo[i], (unsigned)(alo * TOUT + t)));
            khi = umax(khi, packkey(vhi[i], (unsigned)((alo + 1) * TOUT + t)));
        }
    }
    atomicMax(&s_red[2 * l],     klo);
    atomicMax(&s_red[2 * l + 1], khi);
    __syncthreads();
    if (tid < 64) {
        const int c = tbase >> 9;
        atomicMax(&g_cmax[(b * A + a0 + tid) * NCH + c], s_red[tid]);
    }
}

// ---------------- persistent iteration kernel (+ fused output epilogue) ----------------
__global__ void __launch_bounds__(512) persist_kernel(const float* __restrict__ x,
                                                      float* __restrict__ out) {
    extern __shared__ float s_resf[];      // SWZF-indexed private padded residual

    const int blk = blockIdx.x;
    const int b = blk >> 5;
    const int a0 = (blk & 31) * 8;
    const int tid = threadIdx.x;
    const int w = tid >> 5, l = tid & 31;

    __shared__ u64   s_dn2[258 * 4];       // [k][pair], +2 k rows for dp prefetch
    __shared__ u64   s_cm[8 * 33];         // chunk maxima for own 8 atoms
    __shared__ u64   s_red2[8];            // per-warp atom maxima (block reduce)
    __shared__ int   sh_a, sh_p;
    __shared__ float sh_v;

    #pragma unroll 2
    for (int i = tid; i < 258 * 4; i += 512) {
        const int k = i >> 2, p = i & 3;
        s_dn2[i] = (k < 256) ? pack2(g_dn[(a0 + 2 * p) * KA + k],
                                     g_dn[(a0 + 2 * p + 1) * KA + k])
                             : 0ull;
    }
    #pragma unroll 4
    for (int j = tid; j < RES_N; j += 512)
        s_resf[SWZF(j)] = xpad(x, b, j);

    // phase 0: initial chunk maxima -> smem, atom max -> s_red2, 1 ATOMG/block
    if (w < 8) {
        const u64* __restrict__ cm = g_cmax + (size_t)(b * A + a0 + w) * NCH;
        u64 v = cm[l];
        s_cm[w * 33 + l] = v;
        if (l == 0) {
            const u64 v32 = cm[32];
            s_cm[w * 33 + 32] = v32;
            v = umax(v, v32);
        }
        #pragma unroll
        for (int o = 16; o; o >>= 1) v = umax(v, __shfl_xor_sync(0xffffffffu, v, o));
        if (l == 0) s_red2[w] = v;
    }
    __syncthreads();
    if (tid == 0) {
        u64 v = s_red2[0];
        #pragma unroll
        for (int i = 1; i < 8; i++) v = umax(v, s_red2[i]);
        atomicMax(&g_hist[b * NITER + 0], v);
    }

    unsigned target = PBLK;
    gridbar(b, target);                    // hist[0] final

    for (int it = 1; it < NITER; ++it) {
        const bool last = (it == NITER - 1);
        if (tid == 0) decode(g_hist[b * NITER + it - 1], sh_a, sh_p, sh_v);
        __syncthreads();

        const int pos = sh_p;
        const int sa  = sh_a;
        const float sv = sh_v;
        const int lo = max(0, pos - (KA - 1));
        const int hi = min(TOUT - 1, pos + (KA - 1));
        const int c0 = lo >> 9, c1 = hi >> 9;

        if (w >= 8) {
            const int k = (w - 8) * 32 + l;
            s_resf[SWZF(pos + k)] -= sv * g_dn[sa * KA + k];
        } else if (tid < 16) {
            const int at = tid >> 1;
            const int cc = (tid & 1) ? c1 : c0;
            s_cm[at * 33 + cc] = 0ull;
        }
        __syncthreads();

        if (w < 8) {
            const int p = w & 3, h = w >> 2;
            const int t0 = lo + h * 256 + l * 8;

            u64 acc2[8], rbuf[16];
            #pragma unroll
            for (int i = 0; i < 8; i++) acc2[i] = 0ull;
            #pragma unroll
            for (int j = 0; j < 16; j++) {
                const float r = s_resf[SWZF(t0 + j)];
                rbuf[j] = pack2(r, r);
            }

            u64 dp  = s_dn2[p];
            u64 dp1 = s_dn2[4 + p];
            #pragma unroll 1
            for (int k16 = 0; k16 < 256; k16 += 16) {
                #pragma unroll
                for (int kk = 0; kk < 16; kk++) {
                    const u64 dpn = s_dn2[(k16 + kk + 2) * 4 + p];
                    #pragma unroll
                    for (int i = 0; i < 8; i++)
                        ffma2(acc2[i], rbuf[(kk + i) & 15], dp);
                    const float r = s_resf[SWZF(t0 + k16 + kk + 16)];
                    rbuf[kk] = pack2(r, r);
                    dp = dp1; dp1 = dpn;
                }
            }

            float vlo[8], vhi[8];
            #pragma unroll
            for (int i = 0; i < 8; i++) unpack2(acc2[i], vlo[i], vhi[i]);

            const int alo = a0 + 2 * p;
            float* __restrict__ rowlo = g_fm + (size_t)(b * A + alo) * FMS;
            float* __restrict__ rowhi = rowlo + FMS;

            u64 blo0 = 0ull, blo1 = 0ull, bhi0 = 0ull, bhi1 = 0ull;
            #pragma unroll
            for (int i = 0; i < 8; i++) {
                const int t = t0 + i;
                if (t <= hi) {
                    if (!last) {               // no future reader on the last iter
                        rowlo[t] = vlo[i];
                        rowhi[t] = vhi[i];
                    }
                    const u64 klo = packkey(vlo[i], (unsigned)(alo * TOUT + t));
                    const u64 khi = packkey(vhi[i], (unsigned)((alo + 1) * TOUT + t));
                    if ((t >> 9) == c0) { blo0 = umax(blo0, klo); bhi0 = umax(bhi0, khi); }
                    else               { blo1 = umax(blo1, klo); bhi1 = umax(bhi1, khi); }
                }
            }
            #pragma unroll
            for (int o = 16; o; o >>= 1) {
                blo0 = umax(blo0, __shfl_xor_sync(0xffffffffu, blo0, o));
                blo1 = umax(blo1, __shfl_xor_sync(0xffffffffu, blo1, o));
                bhi0 = umax(bhi0, __shfl_xor_sync(0xffffffffu, bhi0, o));
                bhi1 = umax(bhi1, __shfl_xor_sync(0xffffffffu, bhi1, o));
            }
            if (l == 0) {
                atomicMax(&s_cm[(2 * p) * 33 + c0], blo0);
                atomicMax(&s_cm[(2 * p) * 33 + c1], blo1);
                atomicMax(&s_cm[(2 * p + 1) * 33 + c0], bhi0);
                atomicMax(&s_cm[(2 * p + 1) * 33 + c1], bhi1);
            }
        } else {
            const int aw = a0 + (w - 8);
            const int tstart = c0 << 9;
            const int tend = min((c1 + 1) << 9, TOUT);
            const float* __restrict__ rowa = g_fm + (size_t)(b * A + aw) * FMS;
            const unsigned fbase = (unsigned)(aw * TOUT);

            u64 b0 = 0ull, b1 = 0ull;
            #pragma unroll 4
            for (int t = tstart + l; t < tend; t += 32) {
                if (t < lo || t > hi) {
                    const u64 kq = packkey(rowa[t], fbase + t);
                    if ((t >> 9) == c0) b0 = umax(b0, kq); else b1 = umax(b1, kq);
                }
            }
            #pragma unroll
            for (int o = 16; o; o >>= 1) {
                b0 = umax(b0, __shfl_xor_sync(0xffffffffu, b0, o));
                b1 = umax(b1, __shfl_xor_sync(0xffffffffu, b1, o));
            }
            if (l == 0) {
                atomicMax(&s_cm[(w - 8) * 33 + c0], b0);
                atomicMax(&s_cm[(w - 8) * 33 + c1], b1);
            }
        }
        __syncthreads();

        if (w < 8) {
            u64 v = s_cm[w * 33 + l];
            if (l == 0) v = umax(v, s_cm[w * 33 + 32]);
            #pragma unroll
            for (int o = 16; o; o >>= 1)
                v = umax(v, __shfl_xor_sync(0xffffffffu, v, o));
            if (l == 0) s_red2[w] = v;
        }
        __syncthreads();
        if (tid == 0) {
            u64 v = s_red2[0];
            #pragma unroll
            for (int i = 1; i < 8; i++) v = umax(v, s_red2[i]);
            atomicMax(&g_hist[b * NITER + it], v);
        }

        target += PBLK;
        gridbar(b, target);                // hist[it] final
    }

    // ---- fused output epilogue: block writes its 512-output slice ----
    {
        __shared__ int   sa16[NITER], sp16[NITER];
        __shared__ float sv16[NITER];
        if (tid < NITER)
            decode(g_hist[b * NITER + tid], sa16[tid], sp16[tid], sv16[tid]);
        __syncthreads();

        const int t = (blk & 31) * 512 + tid;
        const int tp = t + PAD;
        float acc = 0.f;
        #pragma unroll 1
        for (int j = 0; j < NITER; ++j) {
            const int off = tp - sp16[j];
            if (off >= 0 && off < KA)
                acc += sv16[j] * g_dn[sa16[j] * KA + off];
        }
        out[b * T + t] = acc;
    }
}

// ---------------- launch ----------------
extern "C" void kernel_launch(void* const* d_in, const int* in_sizes, int n_in,
                              void* d_out, int out_size) {
    const float* x = (const float*)d_in[0];
    const float* d = (const float*)d_in[1];
    float* out = (float*)d_out;
    (void)in_sizes; (void)n_in; (void)out_size;

    static int configured = 0;
    if (!configured) {
        cudaFuncSetAttribute(persist_kernel,
                             cudaFuncAttributeMaxDynamicSharedMemorySize, SMEM_DYN);
        configured = 1;
    }

    normd_kernel<<<A, KA>>>(d);
    conv_full_kernel<<<dim3(129, 4, B), 256>>>(x);
    persist_kernel<<<NBLK, 512, SMEM_DYN>>>(x, out);
}